// round 10
// baseline (speedup 1.0000x reference)
#include <cuda_runtime.h>
#include <cuda_fp16.h>
#include <cstdint>

#define EN    262144
#define MROWS 64
#define NCTA  (EN / MROWS)   // 4096
#define NTH   256

// ---------- frag-packed fp16 weights (filled once by pack kernel) ----------
// W1: 24 tiles (chunk*6+slice), tile=[64k x 128n] fp16, 16KB
//     entry 16B at ((kt*8+np)*32+lane)*16 = {nt=2np:r0,r1, nt=2np+1:r0,r1}
__device__ __align__(128) unsigned char g_W1p[24 * 16384];   // 384 KB
// W2: 8 tiles (chunk*2+kslice), 16KB, same format
__device__ __align__(128) unsigned char g_W2p[8 * 16384];    // 128 KB

// ---------- smem layout (per 64-row CTA, 105KB -> 2 CTAs/SM) ----------
// hdr mbars: full0@0 full1@8 empty0@16 empty1@24 w2f@32
#define SM_A    1024        // 6 resident A-frag slices x 8KB = 48KB
#define SM_W10  50176       // W1 ring buf 0 (16KB)
#define SM_W11  66560       // W1 ring buf 1 (16KB)
#define SM_W2   82944       // W2 single k-slice buf (16KB)
#define SM_H    99328       // H frag (8KB)
#define SM_TOT  107520

// ---------- PTX helpers ----------
__device__ __forceinline__ uint32_t smem_u32(const void* p) {
    uint32_t a;
    asm("{ .reg .u64 t; cvta.to.shared.u64 t, %1; cvt.u32.u64 %0, t; }" : "=r"(a) : "l"(p));
    return a;
}
#define MBAR_INIT(a, n)   asm volatile("mbarrier.init.shared.b64 [%0], %1;" :: "r"(a), "r"(n) : "memory")
#define MBAR_EXPECT(a, b) asm volatile("mbarrier.arrive.expect_tx.shared.b64 _, [%0], %1;" :: "r"(a), "r"(b) : "memory")
#define MBAR_ARRIVE(a)    asm volatile("mbarrier.arrive.release.cta.shared.b64 _, [%0];" :: "r"(a) : "memory")
#define MBAR_WAIT(a, ph) do { \
    uint32_t _m = (a), _p = (ph), _d; \
    asm volatile("{ .reg .pred p; mbarrier.try_wait.parity.acquire.cta.shared::cta.b64 p, [%1], %2; selp.b32 %0,1,0,p; }" \
        : "=r"(_d) : "r"(_m), "r"(_p) : "memory"); \
    if (!_d) { \
        asm volatile("{ .reg .pred P1; WL_%=: mbarrier.try_wait.parity.acquire.cta.shared::cta.b64 P1, [%0], %1, 0x989680;\n\t" \
                     "@P1 bra.uni WD_%=; bra.uni WL_%=; WD_%=: }" :: "r"(_m), "r"(_p) : "memory"); \
    } } while (0)

__device__ __forceinline__ void bulk_g2s(uint32_t dst, const void* src, uint32_t bytes, uint32_t bar) {
    asm volatile("cp.async.bulk.shared::cluster.global.mbarrier::complete_tx::bytes [%0], [%1], %2, [%3];"
        :: "r"(dst), "l"(src), "r"(bytes), "r"(bar) : "memory");
}
// pack two fp32 -> f16x2, v0 (lower k) in low 16 bits
__device__ __forceinline__ uint32_t pack2h(float v0, float v1) {
    uint32_t r;
    asm("cvt.rn.f16x2.f32 %0, %1, %2;" : "=r"(r) : "f"(v1), "f"(v0));
    return r;
}
__device__ __forceinline__ void mma_f16(float* c, const uint4& a, uint32_t b0, uint32_t b1) {
    asm volatile("mma.sync.aligned.m16n8k16.row.col.f32.f16.f16.f32 "
        "{%0,%1,%2,%3}, {%4,%5,%6,%7}, {%8,%9}, {%0,%1,%2,%3};"
        : "+f"(c[0]), "+f"(c[1]), "+f"(c[2]), "+f"(c[3])
        : "r"(a.x), "r"(a.y), "r"(a.z), "r"(a.w), "r"(b0), "r"(b1));
}

// ---------- pack kernel (frag-order fp16 weights, n-tile pairs in 16B) ----------
__global__ void pack_w(const float* __restrict__ W1, const float* __restrict__ W2) {
    int idx = blockIdx.x * blockDim.x + threadIdx.x;   // 0..131071
    if (idx < 98304) {           // W1: kp*512 + n
        int kp = idx >> 9, n = idx & 511, k = kp * 2;
        float v0 = W1[(size_t)k * 512 + n], v1 = W1[(size_t)(k + 1) * 512 + n];
        int chunk = n >> 7, slice = k >> 6;
        int kt = (k & 63) >> 4, reg = (k & 15) >> 3;
        int nt = (n & 127) >> 3, np = nt >> 1, sub = nt & 1;
        int lane = (n & 7) * 4 + ((k & 7) >> 1);
        size_t off = (size_t)(chunk * 6 + slice) * 16384
                   + (size_t)((kt * 8 + np) * 32 + lane) * 16 + sub * 8 + reg * 4;
        *(uint32_t*)(g_W1p + off) = pack2h(v0, v1);
    } else {                     // W2: kp*128 + n
        int j = idx - 98304;
        int kp = j >> 7, n = j & 127, k = kp * 2;
        float v0 = W2[(size_t)k * 128 + n], v1 = W2[(size_t)(k + 1) * 128 + n];
        int chunk = k >> 7, ksl = (k >> 6) & 1;
        int kt = (k & 63) >> 4, reg = (k & 15) >> 3;
        int nt = n >> 3, np = nt >> 1, sub = nt & 1;
        int lane = (n & 7) * 4 + ((k & 7) >> 1);
        size_t off = (size_t)(chunk * 2 + ksl) * 16384
                   + (size_t)((kt * 8 + np) * 32 + lane) * 16 + sub * 8 + reg * 4;
        *(uint32_t*)(g_W2p + off) = pack2h(v0, v1);
    }
}

// ---------- main kernel: 64 rows / 256 threads / 2 CTAs per SM ----------
__global__ void __launch_bounds__(NTH, 2) edge_mlp_hmma(
    const float* __restrict__ x_i, const float* __restrict__ x_j,
    const float* __restrict__ edge,
    const float* __restrict__ b1, const float* __restrict__ b2,
    const float* __restrict__ gamma, const float* __restrict__ beta,
    float* __restrict__ out)
{
    extern __shared__ char smem[];
    const uint32_t sb = smem_u32(smem);
    const int tid  = threadIdx.x;
    const int w    = tid >> 5, lane = tid & 31;
    const int mband = w >> 2, nband = w & 3;      // 2 mbands x 4 nbands
    const int row0 = blockIdx.x * MROWS;

    if (tid == 0) {
        MBAR_INIT(sb + 0, 1);    // full0 (tx)
        MBAR_INIT(sb + 8, 1);    // full1 (tx)
        MBAR_INIT(sb + 16, 8);   // empty0 (8 warp arrivals)
        MBAR_INIT(sb + 24, 8);   // empty1
        MBAR_INIT(sb + 32, 1);   // w2 full (tx)
    }
    __syncthreads();

    float acc1[2][4][4];
    float acc2[2][4][4];
#pragma unroll
    for (int a = 0; a < 2; a++)
#pragma unroll
        for (int b = 0; b < 4; b++)
#pragma unroll
            for (int cc = 0; cc < 4; cc++) { acc1[a][b][cc] = 0.f; acc2[a][b][cc] = 0.f; }

    int pf[2] = {0, 0};   // consumer parity for full[b]
    int pe[2] = {0, 0};   // producer parity for empty[b]
    int pw = 0;           // w2 parity

    // conversion-entry geometry: thread handles entries e=tid and e=tid+256 of a slice
    const int e0mt = tid >> 7, e0kt = (tid >> 5) & 3, eln = tid & 31;
    const int r0a = e0mt * 16 + (eln >> 2);
    const int r0b = (e0mt + 2) * 16 + (eln >> 2);
    const int c0a = e0kt * 16 + (eln & 3) * 2;

    // ---- prologue: issue W1 slices 0,1; convert ALL 6 A-slices (resident) ----
    if (tid == 0) {
        MBAR_EXPECT(sb + 0, 16384); bulk_g2s(sb + SM_W10, g_W1p, 16384, sb + 0);
        MBAR_EXPECT(sb + 8, 16384); bulk_g2s(sb + SM_W11, g_W1p + 16384, 16384, sb + 8);
    }
#pragma unroll 1
    for (int ss = 0; ss < 6; ss++) {
        const float* xs = (ss < 2) ? x_i : (ss < 4) ? x_j : edge;
        const int koff = (ss & 1) * 64;
        char* Ab = smem + SM_A + ss * 8192;
        float2 v[8];
#pragma unroll
        for (int ee = 0; ee < 2; ee++) {
            int rr = ee ? r0b : r0a;
            const float* base = xs + (size_t)(row0 + rr) * 128 + koff + c0a;
            v[ee * 4 + 0] = *(const float2*)(base);
            v[ee * 4 + 1] = *(const float2*)(base + 8 * 128);
            v[ee * 4 + 2] = *(const float2*)(base + 8);
            v[ee * 4 + 3] = *(const float2*)(base + 8 * 128 + 8);
        }
#pragma unroll
        for (int ee = 0; ee < 2; ee++) {
            uint4 hv;
            hv.x = pack2h(v[ee * 4 + 0].x, v[ee * 4 + 0].y);
            hv.y = pack2h(v[ee * 4 + 1].x, v[ee * 4 + 1].y);
            hv.z = pack2h(v[ee * 4 + 2].x, v[ee * 4 + 2].y);
            hv.w = pack2h(v[ee * 4 + 3].x, v[ee * 4 + 3].y);
            *(uint4*)(Ab + (uint32_t)(tid + ee * 256) * 16) = hv;
        }
    }
    __syncthreads();   // A frags resident & visible; mbars initialized everywhere

#pragma unroll 1
    for (int c = 0; c < 4; c++) {
        // W2 ksl0 bulk (buffer free: prior chunk's GEMM2 ended with syncthreads)
        if (tid == 0) { MBAR_EXPECT(sb + 32, 16384); bulk_g2s(sb + SM_W2, g_W2p + (size_t)(c * 2) * 16384, 16384, sb + 32); }

        // ===== GEMM1: 6 k-slices, NO CTA barrier (full/empty mbar ring) =====
#pragma unroll 1
        for (int sl = 0; sl < 6; sl++) {
            const int s = c * 6 + sl;
            const int b = s & 1;
            MBAR_WAIT(sb + b * 8, pf[b]); pf[b] ^= 1;        // W1 tile s ready
            const char* Ab = smem + SM_A + sl * 8192;
            const char* Wb = smem + (b ? SM_W11 : SM_W10);
#pragma unroll
            for (int kt = 0; kt < 4; kt++) {
                uint4 ah[2];
#pragma unroll
                for (int m = 0; m < 2; m++)
                    ah[m] = *(const uint4*)(Ab + (uint32_t)(((mband * 2 + m) * 4 + kt) * 32 + lane) * 16);
#pragma unroll
                for (int np = 0; np < 2; np++) {
                    int npg = nband * 2 + np;
                    uint4 Bv = *(const uint4*)(Wb + (uint32_t)((kt * 8 + npg) * 32 + lane) * 16);
                    mma_f16(acc1[0][np * 2],     ah[0], Bv.x, Bv.y);
                    mma_f16(acc1[1][np * 2],     ah[1], Bv.x, Bv.y);
                    mma_f16(acc1[0][np * 2 + 1], ah[0], Bv.z, Bv.w);
                    mma_f16(acc1[1][np * 2 + 1], ah[1], Bv.z, Bv.w);
                }
            }
            // this warp is done with buffer b for slice s
            if (lane == 0) MBAR_ARRIVE(sb + 16 + b * 8);
            // producer: refill buffer b with slice s+2 once all 8 warps arrived
            if (tid == 0 && s + 2 < 24) {
                MBAR_WAIT(sb + 16 + b * 8, pe[b]); pe[b] ^= 1;
                MBAR_EXPECT(sb + b * 8, 16384);
                bulk_g2s(sb + (b ? SM_W11 : SM_W10), g_W1p + (size_t)(s + 2) * 16384, 16384, sb + b * 8);
            }
        }

        // ===== SiLU -> H frags; GEMM2 over 2 k-slices (single W2 buffer) =====
#pragma unroll 1
        for (int ksl = 0; ksl < 2; ksl++) {
            if ((nband >> 1) == ksl) {
#pragma unroll
                for (int t = 0; t < 2; t++) {       // ntp pair (2t,2t+1) -> one STS.128
                    int ntp0 = 2 * t, ntp1 = 2 * t + 1;
                    int colc = nband * 32 + ntp0 * 8 + (lane & 3) * 2;
                    int colg = c * 128 + colc;
                    float b00 = b1[colg],     b01 = b1[colg + 1];
                    float b10 = b1[colg + 8], b11 = b1[colg + 9];
                    int kloc = colc - ksl * 64;
                    int kt_h = kloc >> 4;
#pragma unroll
                    for (int mtp = 0; mtp < 2; mtp++) {
                        uint32_t base = (uint32_t)(((mband * 2 + mtp) * 4 + kt_h) * 32 + lane) * 16;
                        float v0 = acc1[mtp][ntp0][0] + b00;
                        float v1 = acc1[mtp][ntp0][1] + b01;
                        float v2 = acc1[mtp][ntp0][2] + b00;
                        float v3 = acc1[mtp][ntp0][3] + b01;
                        float w0 = acc1[mtp][ntp1][0] + b10;
                        float w1 = acc1[mtp][ntp1][1] + b11;
                        float w2 = acc1[mtp][ntp1][2] + b10;
                        float w3 = acc1[mtp][ntp1][3] + b11;
                        v0 /= (1.0f + __expf(-v0)); v1 /= (1.0f + __expf(-v1));
                        v2 /= (1.0f + __expf(-v2)); v3 /= (1.0f + __expf(-v3));
                        w0 /= (1.0f + __expf(-w0)); w1 /= (1.0f + __expf(-w1));
                        w2 /= (1.0f + __expf(-w2)); w3 /= (1.0f + __expf(-w3));
                        uint4 hv;
                        hv.x = pack2h(v0, v1); hv.y = pack2h(v2, v3);
                        hv.z = pack2h(w0, w1); hv.w = pack2h(w2, w3);
                        *(uint4*)(smem + SM_H + base) = hv;
                    }
                }
            }
            MBAR_WAIT(sb + 32, pw); pw ^= 1;     // W2 k-slice ksl ready
            __syncthreads();                     // H visible to all warps

            const char* Hb  = smem + SM_H;
            const char* W2b = smem + SM_W2;
#pragma unroll
            for (int kt = 0; kt < 4; kt++) {
                uint4 ah[2];
#pragma unroll
                for (int m = 0; m < 2; m++)
                    ah[m] = *(const uint4*)(Hb + (uint32_t)(((mband * 2 + m) * 4 + kt) * 32 + lane) * 16);
#pragma unroll
                for (int np = 0; np < 2; np++) {
                    int npg = nband * 2 + np;
                    uint4 Bv = *(const uint4*)(W2b + (uint32_t)((kt * 8 + npg) * 32 + lane) * 16);
                    mma_f16(acc2[0][np * 2],     ah[0], Bv.x, Bv.y);
                    mma_f16(acc2[1][np * 2],     ah[1], Bv.x, Bv.y);
                    mma_f16(acc2[0][np * 2 + 1], ah[0], Bv.z, Bv.w);
                    mma_f16(acc2[1][np * 2 + 1], ah[1], Bv.z, Bv.w);
                }
            }
            __syncthreads();   // MMA done: H and W2 buffers reusable
            if (ksl == 0 && tid == 0) {
                MBAR_EXPECT(sb + 32, 16384);
                bulk_g2s(sb + SM_W2, g_W2p + (size_t)(c * 2 + 1) * 16384, 16384, sb + 32);
            }
        }
        // reset acc1 for next chunk
#pragma unroll
        for (int a = 0; a < 2; a++)
#pragma unroll
            for (int b = 0; b < 4; b++)
#pragma unroll
                for (int cc = 0; cc < 4; cc++) acc1[a][b][cc] = 0.f;
    }

    // ===== epilogue: stage acc2+b2 (overlay A region), LayerNorm, +edge, store =====
    float* stg = (float*)(smem + SM_A);   // 64 x 130 fp32 = 33.3KB (A region dead)
#pragma unroll
    for (int ntp = 0; ntp < 4; ntp++) {
        int col = nband * 32 + ntp * 8 + (lane & 3) * 2;
        float bb0 = b2[col], bb1 = b2[col + 1];
#pragma unroll
        for (int mtp = 0; mtp < 2; mtp++) {
            int row = mband * 32 + mtp * 16 + (lane >> 2);
            float2 v0 = make_float2(acc2[mtp][ntp][0] + bb0, acc2[mtp][ntp][1] + bb1);
            float2 v1 = make_float2(acc2[mtp][ntp][2] + bb0, acc2[mtp][ntp][3] + bb1);
            *(float2*)(stg + row * 130 + col)       = v0;
            *(float2*)(stg + (row + 8) * 130 + col) = v1;
        }
    }
    __syncthreads();
    if (tid < MROWS) {
        float* rp = stg + tid * 130;
        float s = 0.f, qq = 0.f;
#pragma unroll
        for (int j = 0; j < 128; j += 2) {
            float2 v = *(float2*)(rp + j);
            s += v.x + v.y;
            qq += v.x * v.x + v.y * v.y;
        }
        float mu = s * (1.0f / 128.0f);
        float var = qq * (1.0f / 128.0f) - mu * mu;
        float rs = rsqrtf(var + 1e-5f);
#pragma unroll
        for (int j = 0; j < 128; j += 2) {
            float2 v = *(float2*)(rp + j);
            float2 g = *(const float2*)(gamma + j);
            float2 b = *(const float2*)(beta + j);
            v.x = (v.x - mu) * rs * g.x + b.x;
            v.y = (v.y - mu) * rs * g.y + b.y;
            *(float2*)(rp + j) = v;
        }
    }
    __syncthreads();
#pragma unroll
    for (int it = 0; it < 8; it++) {
        int idx = tid + it * NTH;
        int r = idx >> 5, c4 = idx & 31;
        float2 u0 = *(float2*)(stg + r * 130 + c4 * 4);
        float2 u1 = *(float2*)(stg + r * 130 + c4 * 4 + 2);
        float4 e = *(const float4*)(edge + (size_t)(row0 + r) * 128 + c4 * 4);
        float4 o = make_float4(u0.x + e.x, u0.y + e.y, u1.x + e.z, u1.y + e.w);
        *(float4*)(out + (size_t)(row0 + r) * 128 + c4 * 4) = o;
    }
}

extern "C" void kernel_launch(void* const* d_in, const int* in_sizes, int n_in,
                              void* d_out, int out_size)
{
    const float* x_i   = (const float*)d_in[0];
    const float* x_j   = (const float*)d_in[1];
    const float* edge  = (const float*)d_in[2];
    const float* W1    = (const float*)d_in[3];
    const float* b1    = (const float*)d_in[4];
    const float* W2    = (const float*)d_in[5];
    const float* b2    = (const float*)d_in[6];
    const float* gamma = (const float*)d_in[7];
    const float* beta  = (const float*)d_in[8];
    float* out = (float*)d_out;

    cudaFuncSetAttribute(edge_mlp_hmma, cudaFuncAttributeMaxDynamicSharedMemorySize, SM_TOT);

    pack_w<<<512, 256>>>(W1, W2);
    edge_mlp_hmma<<<NCTA, NTH, SM_TOT>>>(x_i, x_j, edge, b1, b2, gamma, beta, out);
}